// round 2
// baseline (speedup 1.0000x reference)
#include <cuda_runtime.h>
#include <math.h>

// ACT collapses to a per-row scalar recursion:
//   p = sigmoid(x_row . W + b)                 (scalar per row)
//   state = c * x_row  where c follows the same update with x -> 1
//   ponder = nup + rem
// Replicates the reference step's fp32 op order exactly for the scalar part.

#define D 1024
#define THREADS 256
#define MAX_STEPS 20
#define THRESHOLD 0.99f

__global__ __launch_bounds__(THREADS) void act_kernel(
    const float* __restrict__ x,
    const float* __restrict__ W,
    const float* __restrict__ bvec,
    float* __restrict__ out_state,
    float* __restrict__ out_ponder,   // may be null
    int n_rows)
{
    __shared__ float warp_sums[THREADS / 32];
    __shared__ float s_c;
    __shared__ float s_ponder;

    const int t = threadIdx.x;
    const float4 wv = __ldg(&reinterpret_cast<const float4*>(W)[t]);
    const float bb = bvec[0];

    for (int row = blockIdx.x; row < n_rows; row += gridDim.x) {
        const size_t base = (size_t)row * D;

        // Each thread owns one float4 (256 threads * 4 = 1024 = D)
        const float4 xv = reinterpret_cast<const float4*>(x + base)[t];

        float dot = xv.x * wv.x + xv.y * wv.y + xv.z * wv.z + xv.w * wv.w;

        // warp reduce
        #pragma unroll
        for (int o = 16; o > 0; o >>= 1)
            dot += __shfl_xor_sync(0xffffffffu, dot, o);
        if ((t & 31) == 0) warp_sums[t >> 5] = dot;
        __syncthreads();

        if (t == 0) {
            float z = 0.0f;
            #pragma unroll
            for (int i = 0; i < THREADS / 32; i++) z += warp_sums[i];
            z += bb;
            const float p = 1.0f / (1.0f + expf(-z));

            // exact replication of the reference scan in scalar fp32
            float hp = 0.0f, rem = 0.0f, nup = 0.0f, c = 0.0f;
            #pragma unroll
            for (int s = 0; s < MAX_STEPS; s++) {
                float still = (hp < 1.0f) ? 1.0f : 0.0f;
                float nh = ((hp + p * still) > THRESHOLD) ? still : 0.0f;
                hp = hp + p * still;
                rem = rem + nh * (1.0f - hp);
                hp = hp + nh * rem;
                float w = p * still + nh * rem;
                c = (1.0f - w) * c + w;          // x -> 1 in factor space
                nup = nup + still;
            }
            s_c = c;
            s_ponder = nup + rem;
        }
        __syncthreads();

        const float c = s_c;
        float4 ov;
        ov.x = c * xv.x; ov.y = c * xv.y; ov.z = c * xv.z; ov.w = c * xv.w;
        reinterpret_cast<float4*>(out_state + base)[t] = ov;

        if (t == 0 && out_ponder != nullptr)
            out_ponder[row] = s_ponder;
        __syncthreads();   // protect warp_sums/s_c reuse across row iterations
    }
}

extern "C" void kernel_launch(void* const* d_in, const int* in_sizes, int n_in,
                              void* d_out, int out_size) {
    const float* x = (const float*)d_in[0];
    const float* W = (const float*)d_in[1];
    const float* b = (const float*)d_in[2];
    float* out = (float*)d_out;

    const int d = in_sizes[1];           // 1024
    const int n_rows = in_sizes[0] / d;  // B*S = 32768
    (void)n_in;

    // output layout: state (n_rows*D) followed by ponder_time (n_rows), if room
    float* out_ponder = nullptr;
    if ((long long)out_size >= (long long)n_rows * d + n_rows)
        out_ponder = out + (size_t)n_rows * d;

    int blocks = n_rows < 32768 ? n_rows : 32768;
    act_kernel<<<blocks, THREADS>>>(x, W, b, out, out_ponder, n_rows);
}

// round 3
// speedup vs baseline: 1.2357x; 1.2357x over previous
#include <cuda_runtime.h>
#include <math.h>

// ACT collapses to a per-row scalar recursion:
//   p = sigmoid(x_row . W + b)           (scalar per row)
//   state = c * x_row,  c follows the same update with x -> 1
//   ponder = nup + rem
// Warp-per-row, barrier-free: 8 float4 loads per lane (MLP=8), warp shfl
// reduce, all lanes redundantly run the exact fp32 scalar recursion.

#define D 1024
#define THREADS 256          // 8 warps -> 8 rows per block
#define ROWS_PER_BLOCK 8
#define MAX_STEPS 20
#define THRESHOLD 0.99f

__global__ __launch_bounds__(THREADS) void act_kernel(
    const float* __restrict__ x,
    const float* __restrict__ W,
    const float* __restrict__ bvec,
    float* __restrict__ out_state,
    float* __restrict__ out_ponder,   // may be null
    int n_rows)
{
    const int lane = threadIdx.x & 31;
    const int warp = threadIdx.x >> 5;
    const int row  = blockIdx.x * ROWS_PER_BLOCK + warp;
    if (row >= n_rows) return;

    const size_t base = (size_t)row * D;
    const float4* __restrict__ x4 = reinterpret_cast<const float4*>(x + base);
    const float4* __restrict__ w4 = reinterpret_cast<const float4*>(W);

    // Front-batched row load: 8 independent LDG.128 per lane (MLP = 8).
    float4 xv[8];
    #pragma unroll
    for (int i = 0; i < 8; i++)
        xv[i] = x4[i * 32 + lane];

    // Dot with W (L1-hot after first wave).
    float dot = 0.0f;
    #pragma unroll
    for (int i = 0; i < 8; i++) {
        const float4 wv = __ldg(&w4[i * 32 + lane]);
        dot += xv[i].x * wv.x + xv[i].y * wv.y + xv[i].z * wv.z + xv[i].w * wv.w;
    }

    // Warp reduce -> all lanes hold the full row dot.
    #pragma unroll
    for (int o = 16; o > 0; o >>= 1)
        dot += __shfl_xor_sync(0xffffffffu, dot, o);

    const float z = dot + bvec[0];
    const float p = 1.0f / (1.0f + expf(-z));

    // Exact replication of the reference scan in scalar fp32 (all lanes,
    // redundantly — removes any serial/broadcast section).
    float hp = 0.0f, rem = 0.0f, nup = 0.0f, c = 0.0f;
    #pragma unroll
    for (int s = 0; s < MAX_STEPS; s++) {
        float still = (hp < 1.0f) ? 1.0f : 0.0f;
        float nh = ((hp + p * still) > THRESHOLD) ? still : 0.0f;
        hp = hp + p * still;
        rem = rem + nh * (1.0f - hp);
        hp = hp + nh * rem;
        float w = p * still + nh * rem;
        c = (1.0f - w) * c + w;              // x -> 1 in factor space
        nup = nup + still;
    }

    float4* __restrict__ o4 = reinterpret_cast<float4*>(out_state + base);
    #pragma unroll
    for (int i = 0; i < 8; i++) {
        float4 ov;
        ov.x = c * xv[i].x; ov.y = c * xv[i].y;
        ov.z = c * xv[i].z; ov.w = c * xv[i].w;
        o4[i * 32 + lane] = ov;
    }

    if (lane == 0 && out_ponder != nullptr)
        out_ponder[row] = nup + rem;
}

extern "C" void kernel_launch(void* const* d_in, const int* in_sizes, int n_in,
                              void* d_out, int out_size) {
    const float* x = (const float*)d_in[0];
    const float* W = (const float*)d_in[1];
    const float* b = (const float*)d_in[2];
    float* out = (float*)d_out;

    const int d = in_sizes[1];           // 1024
    const int n_rows = in_sizes[0] / d;  // B*S = 32768
    (void)n_in;

    float* out_ponder = nullptr;
    if ((long long)out_size >= (long long)n_rows * d + n_rows)
        out_ponder = out + (size_t)n_rows * d;

    const int blocks = (n_rows + ROWS_PER_BLOCK - 1) / ROWS_PER_BLOCK;
    act_kernel<<<blocks, THREADS>>>(x, W, b, out, out_ponder, n_rows);
}

// round 4
// speedup vs baseline: 1.2415x; 1.0047x over previous
#include <cuda_runtime.h>
#include <math.h>

// ACT collapses to a per-row scalar recursion:
//   p = sigmoid(x_row . W + b)           (scalar per row)
//   state = c * x_row,  c follows the same update with x -> 1
//   ponder = nup + rem
// Two warps per row (64 lanes, 4 float4 each): low register footprint ->
// full occupancy, while keeping MLP=4 independent LDG.128 per thread.
// All lanes redundantly run the exact fp32 scalar recursion.

#define D 1024
#define THREADS 256          // 8 warps -> 4 rows per block (2 warps/row)
#define ROWS_PER_BLOCK 4
#define MAX_STEPS 20
#define THRESHOLD 0.99f

__global__ __launch_bounds__(THREADS, 8) void act_kernel(
    const float* __restrict__ x,
    const float* __restrict__ W,
    const float* __restrict__ bvec,
    float* __restrict__ out_state,
    float* __restrict__ out_ponder,   // may be null
    int n_rows)
{
    __shared__ float warp_part[THREADS / 32];

    const int lane = threadIdx.x & 31;
    const int warp = threadIdx.x >> 5;
    const int half = warp & 1;                      // which half of the row
    const int row  = blockIdx.x * ROWS_PER_BLOCK + (warp >> 1);

    const bool active = (row < n_rows);
    const size_t base = (size_t)row * D;
    const float4* __restrict__ x4 = reinterpret_cast<const float4*>(x + base);
    const float4* __restrict__ w4 = reinterpret_cast<const float4*>(W);

    // Each lane: 4 independent LDG.128 (64 lanes x 4 x 4 floats = 1024 = D).
    // Coalesced: (i, half) selects a contiguous 32-float4 segment.
    float4 xv[4];
    float dot = 0.0f;
    if (active) {
        #pragma unroll
        for (int i = 0; i < 4; i++)
            xv[i] = x4[i * 64 + half * 32 + lane];
        #pragma unroll
        for (int i = 0; i < 4; i++) {
            const float4 wv = __ldg(&w4[i * 64 + half * 32 + lane]);
            dot += xv[i].x * wv.x + xv[i].y * wv.y
                 + xv[i].z * wv.z + xv[i].w * wv.w;
        }
    }

    // Warp-level reduce of this half-row.
    #pragma unroll
    for (int o = 16; o > 0; o >>= 1)
        dot += __shfl_xor_sync(0xffffffffu, dot, o);
    if (lane == 0) warp_part[warp] = dot;
    __syncthreads();

    if (!active) return;

    // Combine the two half-row partials (deterministic order: even + odd).
    const float z = warp_part[warp & ~1] + warp_part[warp | 1] + bvec[0];
    const float p = 1.0f / (1.0f + expf(-z));

    // Exact replication of the reference scan in scalar fp32 (all lanes).
    float hp = 0.0f, rem = 0.0f, nup = 0.0f, c = 0.0f;
    #pragma unroll
    for (int s = 0; s < MAX_STEPS; s++) {
        float still = (hp < 1.0f) ? 1.0f : 0.0f;
        float nh = ((hp + p * still) > THRESHOLD) ? still : 0.0f;
        hp = hp + p * still;
        rem = rem + nh * (1.0f - hp);
        hp = hp + nh * rem;
        float w = p * still + nh * rem;
        c = (1.0f - w) * c + w;              // x -> 1 in factor space
        nup = nup + still;
    }

    float4* __restrict__ o4 = reinterpret_cast<float4*>(out_state + base);
    #pragma unroll
    for (int i = 0; i < 4; i++) {
        float4 ov;
        ov.x = c * xv[i].x; ov.y = c * xv[i].y;
        ov.z = c * xv[i].z; ov.w = c * xv[i].w;
        o4[i * 64 + half * 32 + lane] = ov;
    }

    if (half == 0 && lane == 0 && out_ponder != nullptr)
        out_ponder[row] = nup + rem;
}

extern "C" void kernel_launch(void* const* d_in, const int* in_sizes, int n_in,
                              void* d_out, int out_size) {
    const float* x = (const float*)d_in[0];
    const float* W = (const float*)d_in[1];
    const float* b = (const float*)d_in[2];
    float* out = (float*)d_out;

    const int d = in_sizes[1];           // 1024
    const int n_rows = in_sizes[0] / d;  // B*S = 32768
    (void)n_in;

    float* out_ponder = nullptr;
    if ((long long)out_size >= (long long)n_rows * d + n_rows)
        out_ponder = out + (size_t)n_rows * d;

    const int blocks = (n_rows + ROWS_PER_BLOCK - 1) / ROWS_PER_BLOCK;
    act_kernel<<<blocks, THREADS>>>(x, W, b, out, out_ponder, n_rows);
}